// round 2
// baseline (speedup 1.0000x reference)
#include <cuda_runtime.h>
#include <cstdint>
#include <cstddef>

#define T_DATA 100000
#define NG     24
#define TNO    200
#define ESYN   2000
#define ISYN   500
#define NCB    13
#define NOB    29
#define OLEN   401
#define PAD    256
#define SUFF   1536
#define TPAD   (PAD + T_DATA + SUFF)
#define TILE   1024
#define NELEM  (T_DATA * NG)

// ---------------- device scratch (static, zero-initialized) ----------------
__device__ float g_synE[NG][TPAD];   // transposed per-subunit e-drive, zero pads
__device__ float g_synI[NG][TPAD];
__device__ float g_Zp[TPAD];         // padded copy of Z
__device__ float g_ke[NG][TNO];      // e kernel (unflipped)
__device__ float g_ki[NG][TNO];      // i kernel (negative, unflipped)
__device__ float g_ko[NG][OLEN];     // obs kernel (unflipped)
__device__ int   g_idxE[ESYN];       // synapse -> subunit-1 (or -1 for subunit 0)
__device__ int   g_idxI[ISYN];
__device__ float g_scratchP[NELEM];  // fallback P storage

// ---------------- setup: kernels, connectivity index, Z copy ----------------
__global__ void setup_kernel(const float* __restrict__ Z,
                             const float* __restrict__ Ce,
                             const float* __restrict__ Ci,
                             const float* __restrict__ Wsyn,
                             const float* __restrict__ Wobs,
                             const float* __restrict__ cosb,
                             const float* __restrict__ obsb) {
    int k = blockIdx.x * blockDim.x + threadIdx.x;
    if (k < ESYN) {
        int gf = -1;
        for (int r = 1; r <= NG; ++r)
            if (Ce[r * ESYN + k] != 0.0f) gf = r - 1;
        g_idxE[k] = gf;
        return;
    }
    k -= ESYN;
    if (k < ISYN) {
        int gf = -1;
        for (int r = 1; r <= NG; ++r)
            if (Ci[r * ISYN + k] != 0.0f) gf = r - 1;
        g_idxI[k] = gf;
        return;
    }
    k -= ISYN;
    if (k < NG * TNO) {  // e kernel
        int g = k / TNO, j = k % TNO;
        float s = 0.0f;
        for (int b = 0; b < NCB; ++b) {
            float w = Wsyn[(g * NCB + b) * 2 + 0];
            s += (w * w) * cosb[b * TNO + j];
        }
        g_ke[g][j] = s;
        return;
    }
    k -= NG * TNO;
    if (k < NG * TNO) {  // i kernel (negated)
        int g = k / TNO, j = k % TNO;
        float s = 0.0f;
        for (int b = 0; b < NCB; ++b) {
            float w = Wsyn[(g * NCB + b) * 2 + 1];
            s += (w * w) * cosb[b * TNO + j];
        }
        g_ki[g][j] = -s;
        return;
    }
    k -= NG * TNO;
    if (k < NG * OLEN) {  // obs kernel
        int g = k / OLEN, j = k % OLEN;
        float s = 0.0f;
        for (int b = 0; b < NOB; ++b)
            s += Wobs[g * NOB + b] * obsb[b * OLEN + j];
        g_ko[g][j] = s;
        return;
    }
    k -= NG * OLEN;
    if (k < T_DATA) g_Zp[PAD + k] = Z[k];
}

// ---------------- spike binning: 1 GB streaming, the HBM-bound kernel ------
__global__ void __launch_bounds__(256) bin_kernel(const float4* __restrict__ Se,
                                                  const float4* __restrict__ Si) {
    __shared__ float sb[8][64];   // [row][0..23]=E bins, [32..55]=I bins
    int w = threadIdx.x >> 5, l = threadIdx.x & 31;
    int t0 = blockIdx.x * 8;
    for (int i = threadIdx.x; i < 8 * 64; i += 256) ((float*)sb)[i] = 0.0f;
    __syncthreads();

    int t = t0 + w;
    const float4* rowE = Se + (size_t)t * (ESYN / 4);
    for (int i = l; i < ESYN / 4; i += 32) {
        float4 v = rowE[i];
        if (v.x != 0.0f) { int g = g_idxE[4 * i + 0]; if (g >= 0) atomicAdd(&sb[w][g], v.x); }
        if (v.y != 0.0f) { int g = g_idxE[4 * i + 1]; if (g >= 0) atomicAdd(&sb[w][g], v.y); }
        if (v.z != 0.0f) { int g = g_idxE[4 * i + 2]; if (g >= 0) atomicAdd(&sb[w][g], v.z); }
        if (v.w != 0.0f) { int g = g_idxE[4 * i + 3]; if (g >= 0) atomicAdd(&sb[w][g], v.w); }
    }
    const float4* rowI = Si + (size_t)t * (ISYN / 4);
    for (int i = l; i < ISYN / 4; i += 32) {
        float4 v = rowI[i];
        if (v.x != 0.0f) { int g = g_idxI[4 * i + 0]; if (g >= 0) atomicAdd(&sb[w][32 + g], v.x); }
        if (v.y != 0.0f) { int g = g_idxI[4 * i + 1]; if (g >= 0) atomicAdd(&sb[w][32 + g], v.y); }
        if (v.z != 0.0f) { int g = g_idxI[4 * i + 2]; if (g >= 0) atomicAdd(&sb[w][32 + g], v.z); }
        if (v.w != 0.0f) { int g = g_idxI[4 * i + 3]; if (g >= 0) atomicAdd(&sb[w][32 + g], v.w); }
    }
    __syncthreads();
    for (int kk = threadIdx.x; kk < 8 * 48; kk += 256) {
        int ww = kk & 7, b = kk >> 3;
        int tt = t0 + ww;
        if (b < 24) g_synE[b][PAD + tt] = sb[ww][b];
        else        g_synI[b - 24][PAD + tt] = sb[ww][32 + (b - 24)];
    }
}

// ---------------- fused convs + sigmoid: the FMA-bound kernel ---------------
__global__ void __launch_bounds__(256) glm_kernel(const float* __restrict__ Theta,
                                                  float* Pout_opt) {
    __shared__ __align__(16) float sE[TILE + 200];
    __shared__ __align__(16) float sI[TILE + 200];
    __shared__ __align__(16) float sZ[TILE + 400];
    __shared__ __align__(16) float ske[TNO];   // reversed
    __shared__ __align__(16) float ski[TNO];   // reversed
    __shared__ __align__(16) float sko[404];   // reversed, padded

    float* Pout = Pout_opt ? Pout_opt : (float*)g_scratchP;
    int g = blockIdx.y;
    int t0 = blockIdx.x * TILE;
    int base = PAD + t0 - 200;

    for (int i = threadIdx.x; i < TILE + 200; i += 256) {
        sE[i] = g_synE[g][base + i];
        sI[i] = g_synI[g][base + i];
    }
    for (int i = threadIdx.x; i < TILE + 400; i += 256) sZ[i] = g_Zp[base + i];
    for (int i = threadIdx.x; i < TNO; i += 256) {
        ske[i] = g_ke[g][TNO - 1 - i];
        ski[i] = g_ki[g][TNO - 1 - i];
    }
    for (int i = threadIdx.x; i < 404; i += 256) sko[i] = (i <= 400) ? g_ko[g][OLEN - 1 - i] : 0.0f;
    __syncthreads();

    const int tid = threadIdx.x;
    const int lt = tid * 4;
    float a0 = 0.f, a1 = 0.f, a2 = 0.f, a3 = 0.f;

    // e conv: acc_r += ke_rev[jj] * sE[lt + jj + r], jj = 0..199
    {
        const float4* d4 = (const float4*)sE;
        const float4* k4 = (const float4*)ske;
        float4 cur = d4[tid];
        #pragma unroll 2
        for (int q = 0; q < TNO / 4; ++q) {
            float4 kk = k4[q];
            float4 nxt = d4[tid + q + 1];
            a0 += kk.x * cur.x; a1 += kk.x * cur.y; a2 += kk.x * cur.z; a3 += kk.x * cur.w;
            a0 += kk.y * cur.y; a1 += kk.y * cur.z; a2 += kk.y * cur.w; a3 += kk.y * nxt.x;
            a0 += kk.z * cur.z; a1 += kk.z * cur.w; a2 += kk.z * nxt.x; a3 += kk.z * nxt.y;
            a0 += kk.w * cur.w; a1 += kk.w * nxt.x; a2 += kk.w * nxt.y; a3 += kk.w * nxt.z;
            cur = nxt;
        }
    }
    // i conv
    {
        const float4* d4 = (const float4*)sI;
        const float4* k4 = (const float4*)ski;
        float4 cur = d4[tid];
        #pragma unroll 2
        for (int q = 0; q < TNO / 4; ++q) {
            float4 kk = k4[q];
            float4 nxt = d4[tid + q + 1];
            a0 += kk.x * cur.x; a1 += kk.x * cur.y; a2 += kk.x * cur.z; a3 += kk.x * cur.w;
            a0 += kk.y * cur.y; a1 += kk.y * cur.z; a2 += kk.y * cur.w; a3 += kk.y * nxt.x;
            a0 += kk.z * cur.z; a1 += kk.z * cur.w; a2 += kk.z * nxt.x; a3 += kk.z * nxt.y;
            a0 += kk.w * cur.w; a1 += kk.w * nxt.x; a2 += kk.w * nxt.y; a3 += kk.w * nxt.z;
            cur = nxt;
        }
    }
    // obs conv: 400 taps vectorized + 1 tail tap
    {
        const float4* d4 = (const float4*)sZ;
        const float4* k4 = (const float4*)sko;
        float4 cur = d4[tid];
        #pragma unroll 2
        for (int q = 0; q < 100; ++q) {
            float4 kk = k4[q];
            float4 nxt = d4[tid + q + 1];
            a0 += kk.x * cur.x; a1 += kk.x * cur.y; a2 += kk.x * cur.z; a3 += kk.x * cur.w;
            a0 += kk.y * cur.y; a1 += kk.y * cur.z; a2 += kk.y * cur.w; a3 += kk.y * nxt.x;
            a0 += kk.z * cur.z; a1 += kk.z * cur.w; a2 += kk.z * nxt.x; a3 += kk.z * nxt.y;
            a0 += kk.w * cur.w; a1 += kk.w * nxt.x; a2 += kk.w * nxt.y; a3 += kk.w * nxt.z;
            cur = nxt;
        }
        float kt = sko[400];
        a0 += kt * sZ[lt + 400]; a1 += kt * sZ[lt + 401];
        a2 += kt * sZ[lt + 402]; a3 += kt * sZ[lt + 403];
    }

    float th = Theta[g];
    float acc[4] = {a0, a1, a2, a3};
    int t = t0 + lt;
    #pragma unroll
    for (int r = 0; r < 4; ++r) {
        if (t + r < T_DATA) {
            double x = (double)(acc[r] + th);
            double p = 1.0 / (1.0 + exp(-x));
            Pout[(size_t)(t + r) * NG + g] = (float)p;
        }
    }
}

// ---------------- threefry2x32 + bernoulli --------------------------------
__device__ __forceinline__ uint32_t rotl32(uint32_t x, int r) {
    return (x << r) | (x >> (32 - r));
}
__device__ __forceinline__ void threefry_0_42(uint32_t c0, uint32_t c1,
                                              uint32_t& o0, uint32_t& o1) {
    const uint32_t k0 = 0u, k1 = 42u, k2 = 0x1BD11BDAu ^ 0u ^ 42u;
    uint32_t x0 = c0 + k0, x1 = c1 + k1;
#define RND(r) { x0 += x1; x1 = rotl32(x1, (r)); x1 ^= x0; }
    RND(13) RND(15) RND(26) RND(6)   x0 += k1; x1 += k2 + 1u;
    RND(17) RND(29) RND(16) RND(24)  x0 += k2; x1 += k0 + 2u;
    RND(13) RND(15) RND(26) RND(6)   x0 += k0; x1 += k1 + 3u;
    RND(17) RND(29) RND(16) RND(24)  x0 += k1; x1 += k2 + 4u;
    RND(13) RND(15) RND(26) RND(6)   x0 += k2; x1 += k0 + 5u;
#undef RND
    o0 = x0; o1 = x1;
}

// jax partitionable threefry (default since 0.4.36): per-element 64-bit counter
// (hi=0, lo=i), bits = x0 ^ x1; uniform = bitcast(bits>>9 | 1.0f) - 1.0f; Z = u < P.
__global__ void rng_kernel(const float* Psrc_opt, float* __restrict__ Zo) {
    const float* P = Psrc_opt ? Psrc_opt : (const float*)g_scratchP;
    int i = blockIdx.x * blockDim.x + threadIdx.x;
    if (i >= NELEM) return;
    uint32_t y0, y1;
    threefry_0_42(0u, (uint32_t)i, y0, y1);
    uint32_t bits = y0 ^ y1;
    float u = __uint_as_float((bits >> 9) | 0x3f800000u) - 1.0f;
    Zo[i] = (u < P[i]) ? 1.0f : 0.0f;
}

// ---------------- launcher --------------------------------------------------
extern "C" void kernel_launch(void* const* d_in, const int* in_sizes, int n_in,
                              void* d_out, int out_size) {
    const float *Z = 0, *Se = 0, *Si = 0, *Ce = 0, *Ci = 0;
    const float *Wsyn = 0, *Th = 0, *Wobs = 0, *cb = 0, *ob = 0;
    for (int i = 0; i < n_in; ++i) {
        switch (in_sizes[i]) {
            case 100000:    Z    = (const float*)d_in[i]; break;
            case 200000000: Se   = (const float*)d_in[i]; break;
            case 50000000:  Si   = (const float*)d_in[i]; break;
            case 50000:     Ce   = (const float*)d_in[i]; break;
            case 12500:     Ci   = (const float*)d_in[i]; break;
            case 624:       Wsyn = (const float*)d_in[i]; break;
            case 24:        Th   = (const float*)d_in[i]; break;
            case 696:       Wobs = (const float*)d_in[i]; break;
            case 2600:      cb   = (const float*)d_in[i]; break;
            case 11629:     ob   = (const float*)d_in[i]; break;
            default: break;
        }
    }
    float* out = (float*)d_out;
    float* Pdst = (out_size >= 2 * NELEM) ? (out + NELEM) : nullptr;

    const int setup_work = ESYN + ISYN + NG * TNO + NG * TNO + NG * OLEN + T_DATA;
    setup_kernel<<<(setup_work + 255) / 256, 256>>>(Z, Ce, Ci, Wsyn, Wobs, cb, ob);
    bin_kernel<<<T_DATA / 8, 256>>>((const float4*)Se, (const float4*)Si);
    dim3 gridD((T_DATA + TILE - 1) / TILE, NG);
    glm_kernel<<<gridD, 256>>>(Th, Pdst);
    rng_kernel<<<(NELEM + 255) / 256, 256>>>(Pdst, out);
}